// round 7
// baseline (speedup 1.0000x reference)
#include <cuda_runtime.h>
#include <math.h>

// ---------------- problem constants ----------------
#define BATCH    8192
#define TSTEPS   99
#define DIN      32
#define DH       100
#define GRP      16          // lane-slices per row
#define JT       7           // hidden cols per slice (pad 8 / 12)
#define RW       16
#define RU       25
#define RP       28          // padded rank (phase-1 accumulator width)
#define SL       12          // slice stride (words) in U2/Wc smem
#define U2ROW    192         // = GRP*SL
#define WCROW    192
#define XST      36          // x smem row stride (words)
#define NCLS     6
#define NTHREADS 128
#define ROWS_CTA 16
#define NGRID    (BATCH / ROWS_CTA)        // 512

// smem layout (floats)
#define OFF_U1   0                            // 112*28 = 3136
#define OFF_U2   (OFF_U1 + 112 * RP)          // 25*192 = 4800
#define OFF_WC   (OFF_U2 + RU * U2ROW)        // 32*192 = 6144
#define OFF_BB   (OFF_WC + DIN * WCROW)       // 224
#define OFF_XS   (OFF_BB + 224)               // 2*16*36 = 1152
#define SMEM_FLOATS (OFF_XS + 2 * ROWS_CTA * XST)
#define SMEM_BYTES  (SMEM_FLOATS * 4)         // 61824 B

// ---------------- device-global prepped weights ----------------
__device__ float g_Wcp[DIN * WCROW];        // [k][g*12+c] = (W1@W2)[k][g*7+c]
__device__ float g_U1p[112 * RP];           // [slot = jl*16+g][28]
__device__ float g_U2p[RU * U2ROW];         // [r][g*12+c]
__device__ float g_bb [224];                // interleaved (bias_gate, bias_update)
__device__ float g_sc [2];                  // sigmoid(zeta), sigmoid(nu)

// ---------------- packed f32x2 FMA + tanh.approx ----------------
__device__ __forceinline__ void fma2(float2& d, float2 a, float2 b) {
    asm("fma.rn.f32x2 %0, %1, %2, %0;"
        : "+l"(reinterpret_cast<unsigned long long&>(d))
        : "l"(reinterpret_cast<unsigned long long&>(a)),
          "l"(reinterpret_cast<unsigned long long&>(b)));
}
__device__ __forceinline__ float tanha(float x) {
    float r; asm("tanh.approx.f32 %0, %1;" : "=f"(r) : "f"(x)); return r;
}
__device__ __forceinline__ float elem4(float4 v, int e) {
    return (e == 0) ? v.x : (e == 1) ? v.y : (e == 2) ? v.z : v.w;
}

// ---------------- setup: fold / pad / transpose weights ----------------
__global__ void setup_kernel(const float* __restrict__ W1, const float* __restrict__ W2,
                             const float* __restrict__ U1, const float* __restrict__ U2,
                             const float* __restrict__ bg, const float* __restrict__ bu,
                             const float* __restrict__ zeta, const float* __restrict__ nu) {
    int tid = blockIdx.x * blockDim.x + threadIdx.x;
    int nth = gridDim.x * blockDim.x;
    // Wcp[k][g*12+c] = (W1@W2)[k][g*7+c]  (c<7, j<100)
    for (int idx = tid; idx < DIN * WCROW; idx += nth) {
        int k = idx / WCROW, w = idx % WCROW;
        int g = w / SL, c = w % SL;
        int j = g * JT + c;
        float s = 0.f;
        if (c < JT && j < DH)
            for (int r = 0; r < RW; r++) s = fmaf(W1[k * RW + r], W2[r * DH + j], s);
        g_Wcp[idx] = s;
    }
    // U1p[(jl*16+g)*28 + r] = U1[g*7+jl][r]
    for (int idx = tid; idx < 112 * RP; idx += nth) {
        int slot = idx / RP, r = idx % RP;
        int jl = slot >> 4, g = slot & 15;
        int j = g * JT + jl;
        g_U1p[idx] = (j < DH && r < RU) ? U1[j * RU + r] : 0.f;
    }
    // U2p[r*192 + g*12 + c] = U2[r][g*7+c]  (c<7)
    for (int idx = tid; idx < RU * U2ROW; idx += nth) {
        int r = idx / U2ROW, w = idx % U2ROW;
        int g = w / SL, c = w % SL;
        int j = g * JT + c;
        g_U2p[idx] = (c < JT && j < DH) ? U2[r * DH + j] : 0.f;
    }
    for (int j = tid; j < 112; j += nth) {
        g_bb[2 * j]     = (j < DH) ? bg[j] : 0.f;
        g_bb[2 * j + 1] = (j < DH) ? bu[j] : 0.f;
    }
    if (tid == 0) {
        g_sc[0] = 1.f / (1.f + expf(-zeta[0]));
        g_sc[1] = 1.f / (1.f + expf(-nu[0]));
    }
}

// ---------------- fused recurrent kernel ----------------
__global__ void __launch_bounds__(NTHREADS, 3)
grnn_kernel(const float* __restrict__ x, const float* __restrict__ FC,
            const float* __restrict__ FCb, float* __restrict__ out) {
    extern __shared__ __align__(16) float sm[];
    float* U1s = sm + OFF_U1;
    float* U2s = sm + OFF_U2;
    float* Wcs = sm + OFF_WC;
    float* bbs = sm + OFF_BB;
    float* xs  = sm + OFF_XS;   // [2][ROWS_CTA][XST]

    const int tid = threadIdx.x;
    for (int i = tid; i < 112 * RP; i += NTHREADS) U1s[i] = g_U1p[i];
    for (int i = tid; i < RU * U2ROW; i += NTHREADS) U2s[i] = g_U2p[i];
    for (int i = tid; i < DIN * WCROW; i += NTHREADS) Wcs[i] = g_Wcp[i];
    for (int i = tid; i < 224; i += NTHREADS) bbs[i] = g_bb[i];

    const float sz = g_sc[0];
    const float sn = g_sc[1];

    const int g    = tid & 15;           // slice within row
    const int pr   = tid >> 4;           // row-pair 0..7
    const int r0   = 2 * pr;             // local rows r0, r0+1
    const int rowA = blockIdx.x * ROWS_CTA + r0;
    const float* bbp = bbs + (g * JT) * 2;

    // x staging: thread covers (srow = tid>>3, 4 floats at sf). Rows 4w..4w+3
    // are staged AND consumed by warp w only -> __syncwarp suffices.
    const int srow = tid >> 3;
    const int sf   = (tid & 7) * 4;
    const float* xg = x + (size_t)(blockIdx.x * ROWS_CTA + srow) * (TSTEPS * DIN) + sf;

    // prologue: stage t=0 (plus CTA sync for the weight tables)
    *(float4*)(xs + srow * XST + sf) = *(const float4*)(xg);
    __syncthreads();

    float2 HA[4], HB[4];
#pragma unroll
    for (int i = 0; i < 4; i++) { HA[i] = make_float2(0.f, 0.f); HB[i] = make_float2(0.f, 0.f); }

    int p = 0;
    for (int t = 0; t < TSTEPS; t++) {
        // prefetch next step's x
        const int tn = (t + 1 < TSTEPS) ? (t + 1) : t;
        float4 nx = *(const float4*)(xg + tn * DIN);

        // ---- phase 1: partial Hp = H @ U1 (weights shared across both rows) ----
        float2 pa[RP / 2], pb[RP / 2];
#pragma unroll
        for (int i = 0; i < RP / 2; i++) { pa[i] = make_float2(0.f, 0.f); pb[i] = make_float2(0.f, 0.f); }
#pragma unroll
        for (int jl = 0; jl < JT; jl++) {
            float hA = (jl & 1) ? HA[jl >> 1].y : HA[jl >> 1].x;
            float hB = (jl & 1) ? HB[jl >> 1].y : HB[jl >> 1].x;
            float2 hAv = make_float2(hA, hA);
            float2 hBv = make_float2(hB, hB);
            const float4* urow = (const float4*)(U1s + (jl * GRP + g) * RP);
#pragma unroll
            for (int q = 0; q < 7; q++) {
                float4 u = urow[q];
                float2 ul = make_float2(u.x, u.y);
                float2 uh = make_float2(u.z, u.w);
                fma2(pa[2 * q],     hAv, ul);
                fma2(pa[2 * q + 1], hAv, uh);
                fma2(pb[2 * q],     hBv, ul);
                fma2(pb[2 * q + 1], hBv, uh);
            }
        }
        // ---- butterfly all-reduce over the 16 slice-lanes (r<26 matter) ----
#pragma unroll
        for (int i = 0; i < 13; i++) {
            float ax = pa[i].x, ay = pa[i].y, bx = pb[i].x, by = pb[i].y;
#pragma unroll
            for (int m = 1; m <= 8; m <<= 1) {
                ax += __shfl_xor_sync(0xffffffffu, ax, m);
                ay += __shfl_xor_sync(0xffffffffu, ay, m);
                bx += __shfl_xor_sync(0xffffffffu, bx, m);
                by += __shfl_xor_sync(0xffffffffu, by, m);
            }
            pa[i] = make_float2(ax, ay);
            pb[i] = make_float2(bx, by);
        }

        // ---- phase 2a: c = x @ Wc (slice), both rows ----
        float2 cA[4], cB[4];
#pragma unroll
        for (int i = 0; i < 4; i++) { cA[i] = make_float2(0.f, 0.f); cB[i] = make_float2(0.f, 0.f); }
        const float* xr0 = xs + p * (ROWS_CTA * XST) + r0 * XST;
        const float* xr1 = xr0 + XST;
#pragma unroll
        for (int k4 = 0; k4 < 8; k4++) {
            float4 xa = *(const float4*)(xr0 + k4 * 4);
            float4 xb = *(const float4*)(xr1 + k4 * 4);
#pragma unroll
            for (int e = 0; e < 4; e++) {
                float2 x0v = make_float2(elem4(xa, e), elem4(xa, e));
                float2 x1v = make_float2(elem4(xb, e), elem4(xb, e));
                const float4* w = (const float4*)(Wcs + (k4 * 4 + e) * WCROW + g * SL);
                float4 w0 = w[0], w1 = w[1];
                float2 wl0 = make_float2(w0.x, w0.y);
                float2 wh0 = make_float2(w0.z, w0.w);
                float2 wl1 = make_float2(w1.x, w1.y);
                float2 wh1 = make_float2(w1.z, w1.w);
                fma2(cA[0], x0v, wl0); fma2(cA[1], x0v, wh0);
                fma2(cA[2], x0v, wl1); fma2(cA[3], x0v, wh1);
                fma2(cB[0], x1v, wl0); fma2(cB[1], x1v, wh0);
                fma2(cB[2], x1v, wl1); fma2(cB[3], x1v, wh1);
            }
        }

        // ---- phase 2b: c += Hp @ U2 (slice), both rows ----
#pragma unroll
        for (int r = 0; r < RU; r++) {
            float hpA = (r & 1) ? pa[r >> 1].y : pa[r >> 1].x;
            float hpB = (r & 1) ? pb[r >> 1].y : pb[r >> 1].x;
            float2 hAv = make_float2(hpA, hpA);
            float2 hBv = make_float2(hpB, hpB);
            const float4* u = (const float4*)(U2s + r * U2ROW + g * SL);
            float4 u0 = u[0], u1 = u[1];
            float2 ul0 = make_float2(u0.x, u0.y);
            float2 uh0 = make_float2(u0.z, u0.w);
            float2 ul1 = make_float2(u1.x, u1.y);
            float2 uh1 = make_float2(u1.z, u1.w);
            fma2(cA[0], hAv, ul0); fma2(cA[1], hAv, uh0);
            fma2(cA[2], hAv, ul1); fma2(cA[3], hAv, uh1);
            fma2(cB[0], hBv, ul0); fma2(cB[1], hBv, uh0);
            fma2(cB[2], hBv, ul1); fma2(cB[3], hBv, uh1);
        }

        // ---- elementwise gate/update (sigmoid = 0.5*tanh(z/2)+0.5) ----
#pragma unroll
        for (int jl = 0; jl < JT; jl++) {
            float2 bb = *(const float2*)(bbp + 2 * jl);
            {
                float cc = (jl & 1) ? cA[jl >> 1].y : cA[jl >> 1].x;
                float gg = fmaf(0.5f, tanha(0.5f * (cc + bb.x)), 0.5f);
                float hh = tanha(cc + bb.y);
                float ho = (jl & 1) ? HA[jl >> 1].y : HA[jl >> 1].x;
                float hn = fmaf(gg, ho - sz, fmaf(sn, hh, sz));
                if (jl & 1) HA[jl >> 1].y = hn; else HA[jl >> 1].x = hn;
            }
            {
                float cc = (jl & 1) ? cB[jl >> 1].y : cB[jl >> 1].x;
                float gg = fmaf(0.5f, tanha(0.5f * (cc + bb.x)), 0.5f);
                float hh = tanha(cc + bb.y);
                float ho = (jl & 1) ? HB[jl >> 1].y : HB[jl >> 1].x;
                float hn = fmaf(gg, ho - sz, fmaf(sn, hh, sz));
                if (jl & 1) HB[jl >> 1].y = hn; else HB[jl >> 1].x = hn;
            }
        }

        // ---- publish prefetched x into the other buffer (per-warp private) ----
        *(float4*)(xs + (p ^ 1) * (ROWS_CTA * XST) + srow * XST + sf) = nx;
        __syncwarp();
        p ^= 1;
    }

    // ---- epilogue: score = H @ FC + FCbias ----
    float sA[NCLS], sB[NCLS];
#pragma unroll
    for (int c = 0; c < NCLS; c++) { sA[c] = 0.f; sB[c] = 0.f; }
#pragma unroll
    for (int jl = 0; jl < JT; jl++) {
        int jg = g * JT + jl;
        if (jg < DH) {
            float hA = (jl & 1) ? HA[jl >> 1].y : HA[jl >> 1].x;
            float hB = (jl & 1) ? HB[jl >> 1].y : HB[jl >> 1].x;
#pragma unroll
            for (int c = 0; c < NCLS; c++) {
                float fc = __ldg(FC + jg * NCLS + c);
                sA[c] = fmaf(hA, fc, sA[c]);
                sB[c] = fmaf(hB, fc, sB[c]);
            }
        }
    }
#pragma unroll
    for (int c = 0; c < NCLS; c++) {
#pragma unroll
        for (int m = 1; m <= 8; m <<= 1) {
            sA[c] += __shfl_xor_sync(0xffffffffu, sA[c], m);
            sB[c] += __shfl_xor_sync(0xffffffffu, sB[c], m);
        }
    }
    if (g == 0) {
#pragma unroll
        for (int c = 0; c < NCLS; c++) {
            float fb = __ldg(FCb + c);
            out[(size_t)rowA * NCLS + c]       = sA[c] + fb;
            out[(size_t)(rowA + 1) * NCLS + c] = sB[c] + fb;
        }
    }
}

// ---------------- launch ----------------
extern "C" void kernel_launch(void* const* d_in, const int* in_sizes, int n_in,
                              void* d_out, int out_size) {
    const float* x    = (const float*)d_in[0];
    const float* W1   = (const float*)d_in[1];
    const float* W2   = (const float*)d_in[2];
    const float* U1   = (const float*)d_in[3];
    const float* U2   = (const float*)d_in[4];
    const float* bg   = (const float*)d_in[5];
    const float* bu   = (const float*)d_in[6];
    const float* zeta = (const float*)d_in[7];
    const float* nu   = (const float*)d_in[8];
    const float* FC   = (const float*)d_in[9];
    const float* FCb  = (const float*)d_in[10];
    float* out = (float*)d_out;

    cudaFuncSetAttribute(grnn_kernel, cudaFuncAttributeMaxDynamicSharedMemorySize, SMEM_BYTES);

    setup_kernel<<<32, 256>>>(W1, W2, U1, U2, bg, bu, zeta, nu);
    grnn_kernel<<<NGRID, NTHREADS, SMEM_BYTES>>>(x, FC, FCb, out);
}